// round 5
// baseline (speedup 1.0000x reference)
#include <cuda_runtime.h>
#include <cuda_fp16.h>

// V2STransformer: volume-to-slice affine resample with trilinear interpolation.
// vol: [B,H,W,D] f32 (B=8,H=160,W=160,D=96), trf: [B,S,12] (S=64), out: [B,H,W,S].
//
// Pass 1: transpose+pack with boundary padding and delta form:
//         pair[b][h][d][w] = half2( v, v[w+1 clamped] - v ),  dims [B][H+1][D+1][W]
//         (h=H row duplicates h=H-1; d=D row duplicates d=D-1).
// Pass 2: lanes = w; 4 half2 gathers per sample with immediate offsets
//         (padding removes x1/z1 clamp selects); y-lerp is a single FMA.

#define BB 8
#define HH 160
#define WW 160
#define DD 96
#define SS 64
#define ST_RATIO 1.5f
#define WCHUNK 80
#define HP (HH + 1)   // 161 padded h-planes per batch
#define DP (DD + 1)   // 97 padded d-rows per plane

// Packed pair volume: [b][h(161)][d(97)][w(160)] half2. 79.97 MB.
__device__ __half2 vol_p_buf[(size_t)BB * HP * DP * WW];

// ---------------------------------------------------------------------------
// Pass 1: per-(b,h) half-plane transpose [Wchunk, D] -> [D, Wchunk] + pairing.
// ---------------------------------------------------------------------------
__global__ __launch_bounds__(256)
void v2s_pack_kernel(const float* __restrict__ vol) {
    __shared__ float tile[(WCHUNK + 1) * 97];   // [w_local][d], row stride 97 (odd)

    const int w0 = blockIdx.x * WCHUNK;         // 0 or 80
    const int bh = blockIdx.y;                  // b*HP + h_padded
    const int b  = bh / HP;
    const int hh = bh - b * HP;                 // 0..160
    const int hs = min(hh, HH - 1);             // source h (plane 160 = copy of 159)
    const int tid = threadIdx.x;

    const float* __restrict__ src = vol + ((size_t)b * HH + hs) * WW * DD;  // [w][d]
    __half2* __restrict__ dst = vol_p_buf + (size_t)bh * DP * WW;           // [d][w]

    // Load (WCHUNK+1) w-rows x 96 d, coalesced along d; conflict-free STS.
    #pragma unroll 4
    for (int idx = tid; idx < (WCHUNK + 1) * DD; idx += 256) {
        const int wl = idx / DD;
        const int d  = idx - wl * DD;
        const int w  = min(w0 + wl, WW - 1);    // clamp for the boundary row
        tile[wl * 97 + d] = src[(size_t)w * DD + d];
    }
    __syncthreads();

    // Emit (v, v_next - v) pairs for d rows 0..96 (row 96 = copy of row 95).
    #pragma unroll 4
    for (int idx = tid; idx < DP * WCHUNK; idx += 256) {
        const int d  = idx / WCHUNK;
        const int wl = idx - d * WCHUNK;
        const int ds = min(d, DD - 1);
        const float a = tile[wl * 97 + ds];
        const float c = tile[(wl + 1) * 97 + ds];
        dst[(size_t)d * WW + (w0 + wl)] = __floats2half2_rn(a, c - a);
    }
}

// ---------------------------------------------------------------------------
// Pass 2: main resample. Block = (32 w-lanes, 8), covers (1 h, 32 w, 64 s).
// ---------------------------------------------------------------------------
__global__ __launch_bounds__(256, 4)
void v2s_main_kernel(const float* __restrict__ trf,
                     float* __restrict__ out) {
    // Per-s fused affine partials: coord_r = fmaf(coef_r, fj, P_r).
    __shared__ float Pre[SS][8];             // [s][{cx,Px,cy,Py,cz,Pz,_,_}]
    __shared__ float tile[32][SS + 1];       // [w_local][s]

    const int b  = blockIdx.z;
    const int h  = blockIdx.y;
    const int w0 = blockIdx.x * 32;
    const int tx = threadIdx.x;              // w lane: 0..31
    const int ty = threadIdx.y;              // 0..7
    const int tid = ty * 32 + tx;

    const float fi = (float)h;

    // 64 s * 3 axes = 192 precompute items.
    for (int it = tid; it < SS * 3; it += 256) {
        const int s = it / 3;
        const int r = it - s * 3;
        const float* t = trf + ((size_t)b * SS + s) * 12 + r * 4;
        const float a0 = t[0] + (r == 0 ? 1.0f : 0.0f);
        const float a1 = t[1] + (r == 1 ? 1.0f : 0.0f);
        const float a2 = t[2] + (r == 2 ? 1.0f : 0.0f);
        const float a3 = t[3];
        const float fz = (float)s * ST_RATIO;
        Pre[s][r * 2]     = a1;
        Pre[s][r * 2 + 1] = fmaf(a0, fi, fmaf(a2, fz, a3));
    }
    __syncthreads();

    const __half2* __restrict__ vp = vol_p_buf + (size_t)b * (HP * DP * WW);
    const float fj = (float)(w0 + tx);

    #pragma unroll
    for (int k = 0; k < 8; k++) {
        const int s = ty * 8 + k;            // all lanes in warp share s
        const float4 q  = *reinterpret_cast<const float4*>(&Pre[s][0]);
        const float2 q2 = *reinterpret_cast<const float2*>(&Pre[s][4]);

        float x = fmaf(q.x,  fj, q.y);
        float y = fmaf(q.z,  fj, q.w);
        float z = fmaf(q2.x, fj, q2.y);

        x = fminf(fmaxf(x, 0.0f), (float)(HH - 1));
        y = fminf(fmaxf(y, 0.0f), (float)(WW - 1));
        z = fminf(fmaxf(z, 0.0f), (float)(DD - 1));

        const float xf = floorf(x), yf = floorf(y), zf = floorf(z);
        const float dx = x - xf, dy = y - yf, dz = z - zf;
        const int x0 = (int)xf, y0 = (int)yf, z0 = (int)zf;

        // padded layout: idx = (x*DP + z)*W + y ; neighbors at imm offsets
        const __half2* p = vp + ((x0 * DP + z0) * WW + y0);
        const float2 f00 = __half22float2(__ldg(p));                 // (x0,z0)
        const float2 f01 = __half22float2(__ldg(p + WW));            // (x0,z1)
        const float2 f10 = __half22float2(__ldg(p + DP * WW));       // (x1,z0)
        const float2 f11 = __half22float2(__ldg(p + DP * WW + WW));  // (x1,z1)

        // y-lerp = single FMA (delta form), then z, then x
        const float c00 = fmaf(dy, f00.y, f00.x);
        const float c01 = fmaf(dy, f01.y, f01.x);
        const float c10 = fmaf(dy, f10.y, f10.x);
        const float c11 = fmaf(dy, f11.y, f11.x);
        const float c0  = fmaf(dz, c01 - c00, c00);
        const float c1  = fmaf(dz, c11 - c10, c10);
        const float r   = fmaf(dx, c1 - c0, c0);

        tile[tx][s] = r;
    }
    __syncthreads();

    // Coalesced write: consecutive tids -> consecutive s.
    float* __restrict__ ob = out + (((size_t)b * HH + h) * WW + w0) * SS;
    #pragma unroll
    for (int idx = tid; idx < 32 * SS; idx += 256) {
        const int wl = idx >> 6;
        const int s  = idx & 63;
        ob[(size_t)wl * SS + s] = tile[wl][s];
    }
}

extern "C" void kernel_launch(void* const* d_in, const int* in_sizes, int n_in,
                              void* d_out, int out_size) {
    const float* vol = (const float*)d_in[0];
    const float* trf = (const float*)d_in[1];
    float* out = (float*)d_out;

    {
        dim3 block(256, 1, 1);
        dim3 grid(WW / WCHUNK, BB * HP, 1);     // (2, 1288)
        v2s_pack_kernel<<<grid, block>>>(vol);
    }
    {
        dim3 block(32, 8, 1);
        dim3 grid(WW / 32, HH, BB);             // (5, 160, 8)
        v2s_main_kernel<<<grid, block>>>(trf, out);
    }
}